// round 1
// baseline (speedup 1.0000x reference)
#include <cuda_runtime.h>
#include <cuda_bf16.h>

#define Bn 8
#define Tn 4096
#define Cn 384
#define Hn 6
#define Fn 64
#define En 131072
#define DFF 1536
#define BT (Bn * Tn)             // 32768
#define NEDGE (En + Tn)          // 135168
#define NEG_SLOPE 0.2f
#define LN_EPS 1e-5f

// ---------------- scratch (__device__ globals; no allocation) ----------------
__device__ float g_xn[BT * Cn];      // LN1 output, reused for LN2 output
__device__ float g_h[BT * Cn];       // GAT projection h = xn @ W_gat
__device__ float g_asrc[BT * Hn];
__device__ float g_adst[BT * Hn];
__device__ float g_y1[BT * Cn];      // x + gat_out (residual 1)
__device__ float g_z[BT * DFF];      // FFN hidden
__device__ int   g_cnt[Tn + 1];
__device__ int   g_off[Tn + 1];
__device__ int   g_cur[Tn];
__device__ int   g_csrc[NEDGE];

// ---------------- LayerNorm: one block per row, 128 threads ----------------
__global__ void ln_kernel(const float* __restrict__ x, const float* __restrict__ g,
                          const float* __restrict__ b, float* __restrict__ out) {
    int row = blockIdx.x;
    int tid = threadIdx.x; // 128
    const float* xr = x + (size_t)row * Cn;
    float v0 = xr[tid], v1 = xr[tid + 128], v2 = xr[tid + 256];
    float s  = v0 + v1 + v2;
    float s2 = v0 * v0 + v1 * v1 + v2 * v2;
#pragma unroll
    for (int o = 16; o; o >>= 1) {
        s  += __shfl_xor_sync(0xffffffffu, s,  o);
        s2 += __shfl_xor_sync(0xffffffffu, s2, o);
    }
    __shared__ float ps[4], ps2[4];
    if ((tid & 31) == 0) { ps[tid >> 5] = s; ps2[tid >> 5] = s2; }
    __syncthreads();
    s  = ps[0] + ps[1] + ps[2] + ps[3];
    s2 = ps2[0] + ps2[1] + ps2[2] + ps2[3];
    float mu  = s * (1.0f / Cn);
    float var = s2 * (1.0f / Cn) - mu * mu;
    float inv = rsqrtf(var + LN_EPS);
    float* orow = out + (size_t)row * Cn;
    orow[tid]       = (v0 - mu) * inv * g[tid]       + b[tid];
    orow[tid + 128] = (v1 - mu) * inv * g[tid + 128] + b[tid + 128];
    orow[tid + 256] = (v2 - mu) * inv * g[tid + 256] + b[tid + 256];
}

// ---------------- SGEMM: C[M,N] = A[M,K] @ B[K,N] (+epilogue) ----------------
// MODE 0: plain; MODE 1: bias + relu; MODE 2: bias + residual
template <int MODE>
__global__ void sgemm_kernel(const float* __restrict__ A, const float* __restrict__ Bm,
                             float* __restrict__ Cm, int N, int K,
                             const float* __restrict__ bias,
                             const float* __restrict__ res) {
    const int BM = 64, BN = 64, BK = 16;
    __shared__ float As[BK][BM];
    __shared__ float Bs[BK][BN];
    int tid = threadIdx.x;            // 256
    int bm = blockIdx.y * BM;
    int bn = blockIdx.x * BN;
    int ty = tid >> 4, tx = tid & 15; // 16x16

    int a_r = tid >> 2, a_c = (tid & 3) * 4;  // A tile: 64 rows x 16 cols
    int b_r = tid >> 4, b_c = (tid & 15) * 4; // B tile: 16 rows x 64 cols

    const float* Ap = A + (size_t)(bm + a_r) * K + a_c;
    const float* Bp = Bm + (size_t)b_r * N + bn + b_c;

    float acc[4][4] = {};

    for (int k0 = 0; k0 < K; k0 += BK) {
        float4 av = *(const float4*)(Ap + k0);
        float4 bv = *(const float4*)(Bp + (size_t)k0 * N);
        As[a_c + 0][a_r] = av.x;
        As[a_c + 1][a_r] = av.y;
        As[a_c + 2][a_r] = av.z;
        As[a_c + 3][a_r] = av.w;
        *(float4*)(&Bs[b_r][b_c]) = bv;
        __syncthreads();
#pragma unroll
        for (int k = 0; k < BK; k++) {
            float4 a = *(const float4*)(&As[k][ty * 4]);
            float4 b = *(const float4*)(&Bs[k][tx * 4]);
            acc[0][0] += a.x * b.x; acc[0][1] += a.x * b.y; acc[0][2] += a.x * b.z; acc[0][3] += a.x * b.w;
            acc[1][0] += a.y * b.x; acc[1][1] += a.y * b.y; acc[1][2] += a.y * b.z; acc[1][3] += a.y * b.w;
            acc[2][0] += a.z * b.x; acc[2][1] += a.z * b.y; acc[2][2] += a.z * b.z; acc[2][3] += a.z * b.w;
            acc[3][0] += a.w * b.x; acc[3][1] += a.w * b.y; acc[3][2] += a.w * b.z; acc[3][3] += a.w * b.w;
        }
        __syncthreads();
    }

    int row0 = bm + ty * 4;
    int col0 = bn + tx * 4;
    float4 bb = make_float4(0.f, 0.f, 0.f, 0.f);
    if (MODE != 0) bb = *(const float4*)(bias + col0);
#pragma unroll
    for (int i = 0; i < 4; i++) {
        float4 v = make_float4(acc[i][0], acc[i][1], acc[i][2], acc[i][3]);
        size_t off = (size_t)(row0 + i) * N + col0;
        if (MODE == 1) {
            v.x = fmaxf(v.x + bb.x, 0.f); v.y = fmaxf(v.y + bb.y, 0.f);
            v.z = fmaxf(v.z + bb.z, 0.f); v.w = fmaxf(v.w + bb.w, 0.f);
        } else if (MODE == 2) {
            float4 r = *(const float4*)(res + off);
            v.x += bb.x + r.x; v.y += bb.y + r.y; v.z += bb.z + r.z; v.w += bb.w + r.w;
        }
        *(float4*)(Cm + off) = v;
    }
}

// ---------------- attention coefficients: warp per (node, head) ----------------
__global__ void attn_coef_kernel(const float* __restrict__ Hm,
                                 const float* __restrict__ att_src,
                                 const float* __restrict__ att_dst) {
    int w = blockIdx.x * 8 + (threadIdx.x >> 5);
    int lane = threadIdx.x & 31;
    if (w >= BT * Hn) return;
    int h = w % Hn;
    int n = w / Hn;
    const float* hr = Hm + (size_t)n * Cn + h * Fn;
    float2 hv = ((const float2*)hr)[lane];
    float2 a1 = ((const float2*)(att_src + h * Fn))[lane];
    float2 a2 = ((const float2*)(att_dst + h * Fn))[lane];
    float s1 = hv.x * a1.x + hv.y * a1.y;
    float s2 = hv.x * a2.x + hv.y * a2.y;
#pragma unroll
    for (int o = 16; o; o >>= 1) {
        s1 += __shfl_xor_sync(0xffffffffu, s1, o);
        s2 += __shfl_xor_sync(0xffffffffu, s2, o);
    }
    if (lane == 0) { g_asrc[w] = s1; g_adst[w] = s2; }
}

// ---------------- CSR build ----------------
__global__ void zero_cnt_kernel() {
    int i = blockIdx.x * blockDim.x + threadIdx.x;
    if (i <= Tn) g_cnt[i] = 0;
}

__global__ void hist_kernel(const int* __restrict__ edge_dst) {
    int e = blockIdx.x * blockDim.x + threadIdx.x;
    if (e >= NEDGE) return;
    int d = (e < En) ? edge_dst[e] : (e - En);
    atomicAdd(&g_cnt[d], 1);
}

__global__ void scan_kernel() {
    __shared__ int sm[1024];
    int t = threadIdx.x; // 1024, Tn/4 groups
    int c0 = g_cnt[4 * t + 0], c1 = g_cnt[4 * t + 1];
    int c2 = g_cnt[4 * t + 2], c3 = g_cnt[4 * t + 3];
    int val = c0 + c1 + c2 + c3;
    sm[t] = val;
    __syncthreads();
    for (int d = 1; d < 1024; d <<= 1) {
        int v = (t >= d) ? sm[t - d] : 0;
        __syncthreads();
        if (t >= d) sm[t] += v;
        __syncthreads();
    }
    int base = sm[t] - val; // exclusive prefix of this group
    int o0 = base, o1 = base + c0, o2 = base + c0 + c1, o3 = base + c0 + c1 + c2;
    g_off[4 * t + 0] = o0; g_cur[4 * t + 0] = o0;
    g_off[4 * t + 1] = o1; g_cur[4 * t + 1] = o1;
    g_off[4 * t + 2] = o2; g_cur[4 * t + 2] = o2;
    g_off[4 * t + 3] = o3; g_cur[4 * t + 3] = o3;
    if (t == 1023) g_off[Tn] = sm[1023];
}

__global__ void scatter_kernel(const int* __restrict__ edge_src,
                               const int* __restrict__ edge_dst) {
    int e = blockIdx.x * blockDim.x + threadIdx.x;
    if (e >= NEDGE) return;
    int s, d;
    if (e < En) { s = edge_src[e]; d = edge_dst[e]; }
    else        { s = e - En;      d = e - En; }
    int p = atomicAdd(&g_cur[d], 1);
    g_csrc[p] = s;
}

// ---------------- GAT aggregation: warp per (batch, dst node, head) ----------------
__global__ void gat_agg_kernel(const float* __restrict__ Hm,
                               const float* __restrict__ asrc,
                               const float* __restrict__ adst,
                               const float* __restrict__ x,
                               const float* __restrict__ bgat,
                               float* __restrict__ y1) {
    int w = blockIdx.x * 8 + (threadIdx.x >> 5);
    int lane = threadIdx.x & 31;
    if (w >= Bn * Tn * Hn) return;
    int h = w % Hn;
    int n = w / Hn;     // b*T + t
    int t = n % Tn;
    int b = n / Tn;
    int beg = g_off[t], end = g_off[t + 1];
    const float* asrc_b = asrc + (size_t)b * Tn * Hn;
    float a_d = adst[(size_t)n * Hn + h];

    // pass 1: segment max of leaky-relu'd alpha
    float m = -1e30f;
    for (int e = beg + lane; e < end; e += 32) {
        int s = g_csrc[e];
        float al = asrc_b[s * Hn + h] + a_d;
        al = (al >= 0.f) ? al : NEG_SLOPE * al;
        m = fmaxf(m, al);
    }
#pragma unroll
    for (int o = 16; o; o >>= 1) m = fmaxf(m, __shfl_xor_sync(0xffffffffu, m, o));

    // pass 2: weighted sum of h[src] (lanes own 2 feature elems each)
    const float* Hb = Hm + (size_t)b * Tn * Cn;
    float den = 0.f, acc0 = 0.f, acc1 = 0.f;
    for (int e = beg; e < end; e++) {
        int s = g_csrc[e];
        float al = asrc_b[s * Hn + h] + a_d;
        al = (al >= 0.f) ? al : NEG_SLOPE * al;
        float wgt = __expf(al - m);
        den += wgt;
        float2 hv = *(const float2*)(Hb + (size_t)s * Cn + h * Fn + lane * 2);
        acc0 += wgt * hv.x;
        acc1 += wgt * hv.y;
    }
    float inv = 1.f / den;
    int c = h * Fn + lane * 2;
    size_t o = (size_t)n * Cn + c;
    float2 xo = *(const float2*)(x + o);
    float2 bg = *(const float2*)(bgat + c);
    float2 r;
    r.x = xo.x + acc0 * inv + bg.x;
    r.y = xo.y + acc1 * inv + bg.y;
    *(float2*)(y1 + o) = r;
}

// ---------------- launch ----------------
extern "C" void kernel_launch(void* const* d_in, const int* in_sizes, int n_in,
                              void* d_out, int out_size) {
    const float* x        = (const float*)d_in[0];
    const int*   edge     = (const int*)d_in[1];
    const float* W_gat    = (const float*)d_in[2];
    const float* att_src  = (const float*)d_in[3];
    const float* att_dst  = (const float*)d_in[4];
    const float* b_gat    = (const float*)d_in[5];
    const float* ln1_g    = (const float*)d_in[6];
    const float* ln1_b    = (const float*)d_in[7];
    const float* ln2_g    = (const float*)d_in[8];
    const float* ln2_b    = (const float*)d_in[9];
    const float* W1       = (const float*)d_in[10];
    const float* b1       = (const float*)d_in[11];
    const float* W2       = (const float*)d_in[12];
    const float* b2       = (const float*)d_in[13];
    float* out = (float*)d_out;

    const int* edge_src = edge;
    const int* edge_dst = edge + En;

    float *xn, *hmat, *asrc, *adst, *y1, *z;
    cudaGetSymbolAddress((void**)&xn,   g_xn);
    cudaGetSymbolAddress((void**)&hmat, g_h);
    cudaGetSymbolAddress((void**)&asrc, g_asrc);
    cudaGetSymbolAddress((void**)&adst, g_adst);
    cudaGetSymbolAddress((void**)&y1,   g_y1);
    cudaGetSymbolAddress((void**)&z,    g_z);

    // CSR build (graph shared across batch)
    zero_cnt_kernel<<<(Tn + 256) / 256, 256>>>();
    hist_kernel<<<(NEDGE + 255) / 256, 256>>>(edge_dst);
    scan_kernel<<<1, 1024>>>();
    scatter_kernel<<<(NEDGE + 255) / 256, 256>>>(edge_src, edge_dst);

    // LN1
    ln_kernel<<<BT, 128>>>(x, ln1_g, ln1_b, xn);
    // h = xn @ W_gat
    sgemm_kernel<0><<<dim3(Cn / 64, BT / 64), 256>>>(xn, W_gat, hmat, Cn, Cn, nullptr, nullptr);
    // attention coefficients
    attn_coef_kernel<<<(BT * Hn) / 8, 256>>>(hmat, att_src, att_dst);
    // segment softmax + aggregation + residual + bias
    gat_agg_kernel<<<(Bn * Tn * Hn) / 8, 256>>>(hmat, asrc, adst, x, b_gat, y1);
    // LN2 (reuse xn buffer)
    ln_kernel<<<BT, 128>>>(y1, ln2_g, ln2_b, xn);
    // FFN
    sgemm_kernel<1><<<dim3(DFF / 64, BT / 64), 256>>>(xn, W1, z, DFF, Cn, b1, nullptr);
    sgemm_kernel<2><<<dim3(Cn / 64, BT / 64), 256>>>(z, W2, out, Cn, DFF, b2, y1);
}

// round 4
// speedup vs baseline: 4.6934x; 4.6934x over previous
#include <cuda_runtime.h>
#include <cuda_bf16.h>
#include <cstdint>

#define Bn 8
#define Tn 4096
#define Cn 384
#define Hn 6
#define Fn 64
#define En 131072
#define DFF 1536
#define BT (Bn * Tn)             // 32768
#define NEDGE (En + Tn)          // 135168
#define NEG_SLOPE 0.2f
#define LN_EPS 1e-5f

// ---------------- scratch (__device__ globals; no allocation) ----------------
__device__ __nv_bfloat16 g_xnb[BT * Cn];     // LN output (bf16), reused LN1/LN2
__device__ float         g_h[BT * Cn];       // GAT projection h (fp32)
__device__ float         g_asrc[BT * Hn];
__device__ float         g_adst[BT * Hn];
__device__ float         g_y1[BT * Cn];      // x + gat_out (residual 1, fp32)
__device__ __nv_bfloat16 g_z[BT * DFF];      // FFN hidden (bf16)
__device__ __nv_bfloat16 g_w1t[DFF * Cn];    // W1^T  [DFF][C]
__device__ __nv_bfloat16 g_w2t[Cn * DFF];    // W2^T  [C][DFF]
__device__ __nv_bfloat16 g_wgt[Cn * Cn];     // W_gat^T
__device__ int g_cnt[Tn + 1];
__device__ int g_off[Tn + 1];
__device__ int g_cur[Tn];
__device__ int g_csrc[NEDGE];

// ---------------- PTX helpers ----------------
__device__ __forceinline__ uint32_t smem_u32(const void* p) {
    uint32_t a;
    asm("{ .reg .u64 t; cvta.to.shared.u64 t, %1; cvt.u32.u64 %0, t; }" : "=r"(a) : "l"(p));
    return a;
}
__device__ __forceinline__ void cp_async16(uint32_t dst, const void* src) {
    asm volatile("cp.async.cg.shared.global [%0], [%1], 16;" :: "r"(dst), "l"(src) : "memory");
}
__device__ __forceinline__ void cp_commit() {
    asm volatile("cp.async.commit_group;" ::: "memory");
}
__device__ __forceinline__ void cp_wait1() {
    asm volatile("cp.async.wait_group 1;" ::: "memory");
}
__device__ __forceinline__ void cp_wait0() {
    asm volatile("cp.async.wait_group 0;" ::: "memory");
}
__device__ __forceinline__ void ldmat_x4(uint32_t& r0, uint32_t& r1, uint32_t& r2, uint32_t& r3,
                                         uint32_t addr) {
    asm volatile("ldmatrix.sync.aligned.m8n8.x4.shared.b16 {%0,%1,%2,%3}, [%4];"
                 : "=r"(r0), "=r"(r1), "=r"(r2), "=r"(r3) : "r"(addr));
}
__device__ __forceinline__ void mma_bf16(float* d, const uint32_t* a, const uint32_t* b) {
    asm volatile(
        "mma.sync.aligned.m16n8k16.row.col.f32.bf16.bf16.f32 "
        "{%0,%1,%2,%3}, {%4,%5,%6,%7}, {%8,%9}, {%0,%1,%2,%3};"
        : "+f"(d[0]), "+f"(d[1]), "+f"(d[2]), "+f"(d[3])
        : "r"(a[0]), "r"(a[1]), "r"(a[2]), "r"(a[3]), "r"(b[0]), "r"(b[1]));
}

// SW64 swizzle for 64-byte smem rows (conflict-free for ldmatrix + cp.async)
__device__ __forceinline__ uint32_t sw64(uint32_t off) {
    return off ^ ((off >> 3) & 0x30);
}

// ---------------- bf16 HMMA GEMM: D[M,N] = A[M,K] @ Bt[N,K]^T ----------------
// MODE 0: fp32 out plain; MODE 1: bf16 out bias+relu; MODE 2: fp32 out bias+residual
// 128x128 CTA tile, BK=32, double-buffered cp.async, 8 warps (2M x 4N), warp 64x32.
template <int N, int K, int MODE>
__global__ __launch_bounds__(256, 2) void gemm_mma(
    const __nv_bfloat16* __restrict__ A,
    const __nv_bfloat16* __restrict__ Bt,
    const float* __restrict__ bias,
    const float* __restrict__ res,
    float* __restrict__ outf,
    __nv_bfloat16* __restrict__ outb)
{
    __shared__ __align__(1024) unsigned char smem[32768]; // [stage][A 8KB | B 8KB]
    const uint32_t sbase = smem_u32(smem);

    int tid = threadIdx.x;
    int wid = tid >> 5;
    int lane = tid & 31;
    int bm = blockIdx.y * 128;
    int bn = blockIdx.x * 128;
    int wm = (wid & 1) * 64;
    int wn = (wid >> 1) * 32;

    float acc[4][4][4];
#pragma unroll
    for (int i = 0; i < 4; i++)
#pragma unroll
        for (int j = 0; j < 4; j++)
#pragma unroll
            for (int d = 0; d < 4; d++) acc[i][j][d] = 0.f;

    const int KT = K / 32;

    // stage loader: A tile 128x32 (512 x16B), B tile 128x32 (512 x16B)
    auto load_stage = [&](int kt, int s) {
        int k0 = kt * 32;
        uint32_t sA = sbase + s * 16384;
        uint32_t sB = sA + 8192;
#pragma unroll
        for (int i = 0; i < 2; i++) {
            int idx = tid + i * 256;          // 0..511
            int r = idx >> 2, c = idx & 3;
            uint32_t sw = sw64(r * 64 + c * 16);
            cp_async16(sA + sw, A + (size_t)(bm + r) * K + k0 + c * 8);
            cp_async16(sB + sw, Bt + (size_t)(bn + r) * K + k0 + c * 8);
        }
    };

    load_stage(0, 0);
    cp_commit();

    for (int kt = 0; kt < KT; kt++) {
        if (kt + 1 < KT) {
            load_stage(kt + 1, (kt + 1) & 1);
            cp_commit();
            cp_wait1();
        } else {
            cp_wait0();
        }
        __syncthreads();

        uint32_t sA = sbase + (kt & 1) * 16384;
        uint32_t sB = sA + 8192;
#pragma unroll
        for (int ks = 0; ks < 2; ks++) {
            uint32_t af[4][4];
            uint32_t bf[4][2];
#pragma unroll
            for (int mi = 0; mi < 4; mi++) {
                int row = wm + mi * 16 + (lane & 15);
                int colb = (ks * 16 + ((lane >> 4) << 3)) * 2;
                ldmat_x4(af[mi][0], af[mi][1], af[mi][2], af[mi][3],
                         sA + sw64(row * 64 + colb));
            }
#pragma unroll
            for (int nj = 0; nj < 2; nj++) {
                int nrow = wn + nj * 16 + (lane & 7) + ((lane >> 4) << 3);
                int kcolb = (ks * 16 + (((lane >> 3) & 1) << 3)) * 2;
                uint32_t r0, r1, r2, r3;
                ldmat_x4(r0, r1, r2, r3, sB + sw64(nrow * 64 + kcolb));
                bf[nj * 2][0] = r0; bf[nj * 2][1] = r1;
                bf[nj * 2 + 1][0] = r2; bf[nj * 2 + 1][1] = r3;
            }
#pragma unroll
            for (int mi = 0; mi < 4; mi++)
#pragma unroll
                for (int ni = 0; ni < 4; ni++)
                    mma_bf16(acc[mi][ni], af[mi], bf[ni]);
        }
        __syncthreads();
    }

    // Epilogue: direct global stores. acc tile (mi,ni): rows gm+lane/4 (+8), cols gn+(lane%4)*2.
    int rq = lane >> 2;
    int cq = (lane & 3) * 2;
#pragma unroll
    for (int mi = 0; mi < 4; mi++) {
#pragma unroll
        for (int ni = 0; ni < 4; ni++) {
            int gm = bm + wm + mi * 16 + rq;
            int gn = bn + wn + ni * 8 + cq;
            float v0 = acc[mi][ni][0], v1 = acc[mi][ni][1];
            float v2 = acc[mi][ni][2], v3 = acc[mi][ni][3];
            if (MODE == 0) {
                *(float2*)(outf + (size_t)gm * N + gn) = make_float2(v0, v1);
                *(float2*)(outf + (size_t)(gm + 8) * N + gn) = make_float2(v2, v3);
            } else if (MODE == 1) {
                float b0 = bias[gn], b1 = bias[gn + 1];
                __nv_bfloat162 p0, p1;
                p0.x = __float2bfloat16(fmaxf(v0 + b0, 0.f));
                p0.y = __float2bfloat16(fmaxf(v1 + b1, 0.f));
                p1.x = __float2bfloat16(fmaxf(v2 + b0, 0.f));
                p1.y = __float2bfloat16(fmaxf(v3 + b1, 0.f));
                *(__nv_bfloat162*)(outb + (size_t)gm * N + gn) = p0;
                *(__nv_bfloat162*)(outb + (size_t)(gm + 8) * N + gn) = p1;
            } else {
                float b0 = bias[gn], b1 = bias[gn + 1];
                float2 r0 = *(const float2*)(res + (size_t)gm * N + gn);
                float2 r1 = *(const float2*)(res + (size_t)(gm + 8) * N + gn);
                *(float2*)(outf + (size_t)gm * N + gn) = make_float2(v0 + b0 + r0.x, v1 + b1 + r0.y);
                *(float2*)(outf + (size_t)(gm + 8) * N + gn) = make_float2(v2 + b0 + r1.x, v3 + b1 + r1.y);
            }
        }
    }
}

// ---------------- weight transpose + fp32->bf16 ----------------
__global__ void transpose_bf16(const float* __restrict__ src, __nv_bfloat16* __restrict__ dst,
                               int Rs, int Cs) {
    __shared__ float t[32][33];
    int c = blockIdx.x * 32 + threadIdx.x;
    int r = blockIdx.y * 32 + threadIdx.y;
    t[threadIdx.y][threadIdx.x] = src[(size_t)r * Cs + c];
    __syncthreads();
    int oc = blockIdx.y * 32 + threadIdx.x;
    int orr = blockIdx.x * 32 + threadIdx.y;
    dst[(size_t)orr * Rs + oc] = __float2bfloat16(t[threadIdx.x][threadIdx.y]);
}

// ---------------- LayerNorm (fp32 in, bf16 out) ----------------
__global__ void ln_bf16_kernel(const float* __restrict__ x, const float* __restrict__ g,
                               const float* __restrict__ b, __nv_bfloat16* __restrict__ out) {
    int row = blockIdx.x;
    int tid = threadIdx.x; // 128
    const float* xr = x + (size_t)row * Cn;
    float v0 = xr[tid], v1 = xr[tid + 128], v2 = xr[tid + 256];
    float s  = v0 + v1 + v2;
    float s2 = v0 * v0 + v1 * v1 + v2 * v2;
#pragma unroll
    for (int o = 16; o; o >>= 1) {
        s  += __shfl_xor_sync(0xffffffffu, s,  o);
        s2 += __shfl_xor_sync(0xffffffffu, s2, o);
    }
    __shared__ float ps[4], ps2[4];
    if ((tid & 31) == 0) { ps[tid >> 5] = s; ps2[tid >> 5] = s2; }
    __syncthreads();
    s  = ps[0] + ps[1] + ps[2] + ps[3];
    s2 = ps2[0] + ps2[1] + ps2[2] + ps2[3];
    float mu  = s * (1.0f / Cn);
    float var = s2 * (1.0f / Cn) - mu * mu;
    float inv = rsqrtf(var + LN_EPS);
    __nv_bfloat16* orow = out + (size_t)row * Cn;
    orow[tid]       = __float2bfloat16((v0 - mu) * inv * g[tid]       + b[tid]);
    orow[tid + 128] = __float2bfloat16((v1 - mu) * inv * g[tid + 128] + b[tid + 128]);
    orow[tid + 256] = __float2bfloat16((v2 - mu) * inv * g[tid + 256] + b[tid + 256]);
}

// ---------------- attention coefficients: warp per (node, head) ----------------
__global__ void attn_coef_kernel(const float* __restrict__ Hm,
                                 const float* __restrict__ att_src,
                                 const float* __restrict__ att_dst) {
    int w = blockIdx.x * 8 + (threadIdx.x >> 5);
    int lane = threadIdx.x & 31;
    if (w >= BT * Hn) return;
    int h = w % Hn;
    int n = w / Hn;
    const float* hr = Hm + (size_t)n * Cn + h * Fn;
    float2 hv = ((const float2*)hr)[lane];
    float2 a1 = ((const float2*)(att_src + h * Fn))[lane];
    float2 a2 = ((const float2*)(att_dst + h * Fn))[lane];
    float s1 = hv.x * a1.x + hv.y * a1.y;
    float s2 = hv.x * a2.x + hv.y * a2.y;
#pragma unroll
    for (int o = 16; o; o >>= 1) {
        s1 += __shfl_xor_sync(0xffffffffu, s1, o);
        s2 += __shfl_xor_sync(0xffffffffu, s2, o);
    }
    if (lane == 0) { g_asrc[w] = s1; g_adst[w] = s2; }
}

// ---------------- CSR build ----------------
__global__ void zero_cnt_kernel() {
    int i = blockIdx.x * blockDim.x + threadIdx.x;
    if (i <= Tn) g_cnt[i] = 0;
}
__global__ void hist_kernel(const int* __restrict__ edge_dst) {
    int e = blockIdx.x * blockDim.x + threadIdx.x;
    if (e >= NEDGE) return;
    int d = (e < En) ? edge_dst[e] : (e - En);
    atomicAdd(&g_cnt[d], 1);
}
__global__ void scan_kernel() {
    __shared__ int sm[1024];
    int t = threadIdx.x;
    int c0 = g_cnt[4 * t + 0], c1 = g_cnt[4 * t + 1];
    int c2 = g_cnt[4 * t + 2], c3 = g_cnt[4 * t + 3];
    int val = c0 + c1 + c2 + c3;
    sm[t] = val;
    __syncthreads();
    for (int d = 1; d < 1024; d <<= 1) {
        int v = (t >= d) ? sm[t - d] : 0;
        __syncthreads();
        if (t >= d) sm[t] += v;
        __syncthreads();
    }
    int base = sm[t] - val;
    g_off[4 * t + 0] = base;                g_cur[4 * t + 0] = base;
    g_off[4 * t + 1] = base + c0;           g_cur[4 * t + 1] = base + c0;
    g_off[4 * t + 2] = base + c0 + c1;      g_cur[4 * t + 2] = base + c0 + c1;
    g_off[4 * t + 3] = base + c0 + c1 + c2; g_cur[4 * t + 3] = base + c0 + c1 + c2;
    if (t == 1023) g_off[Tn] = sm[1023];
}
__global__ void scatter_kernel(const int* __restrict__ edge_src,
                               const int* __restrict__ edge_dst) {
    int e = blockIdx.x * blockDim.x + threadIdx.x;
    if (e >= NEDGE) return;
    int s, d;
    if (e < En) { s = edge_src[e]; d = edge_dst[e]; }
    else        { s = e - En;      d = e - En; }
    int p = atomicAdd(&g_cur[d], 1);
    g_csrc[p] = s;
}

// ---------------- GAT aggregation: warp per (batch, dst node, head) ----------------
__global__ void gat_agg_kernel(const float* __restrict__ Hm,
                               const float* __restrict__ asrc,
                               const float* __restrict__ adst,
                               const float* __restrict__ x,
                               const float* __restrict__ bgat,
                               float* __restrict__ y1) {
    int w = blockIdx.x * 8 + (threadIdx.x >> 5);
    int lane = threadIdx.x & 31;
    if (w >= Bn * Tn * Hn) return;
    int h = w % Hn;
    int n = w / Hn;
    int t = n % Tn;
    int b = n / Tn;
    int beg = g_off[t], end = g_off[t + 1];
    const float* asrc_b = asrc + (size_t)b * Tn * Hn;
    float a_d = adst[(size_t)n * Hn + h];

    float m = -1e30f;
    for (int e = beg + lane; e < end; e += 32) {
        int s = g_csrc[e];
        float al = asrc_b[s * Hn + h] + a_d;
        al = (al >= 0.f) ? al : NEG_SLOPE * al;
        m = fmaxf(m, al);
    }
#pragma unroll
    for (int o = 16; o; o >>= 1) m = fmaxf(m, __shfl_xor_sync(0xffffffffu, m, o));

    const float* Hb = Hm + (size_t)b * Tn * Cn;
    float den = 0.f, acc0 = 0.f, acc1 = 0.f;
#pragma unroll 2
    for (int e = beg; e < end; e++) {
        int s = g_csrc[e];
        float al = asrc_b[s * Hn + h] + a_d;
        al = (al >= 0.f) ? al : NEG_SLOPE * al;
        float wgt = __expf(al - m);
        den += wgt;
        float2 hv = *(const float2*)(Hb + (size_t)s * Cn + h * Fn + lane * 2);
        acc0 += wgt * hv.x;
        acc1 += wgt * hv.y;
    }
    float inv = 1.f / den;
    int c = h * Fn + lane * 2;
    size_t o = (size_t)n * Cn + c;
    float2 xo = *(const float2*)(x + o);
    float2 bg = *(const float2*)(bgat + c);
    float2 r;
    r.x = xo.x + acc0 * inv + bg.x;
    r.y = xo.y + acc1 * inv + bg.y;
    *(float2*)(y1 + o) = r;
}

// ---------------- launch ----------------
extern "C" void kernel_launch(void* const* d_in, const int* in_sizes, int n_in,
                              void* d_out, int out_size) {
    const float* x        = (const float*)d_in[0];
    const int*   edge     = (const int*)d_in[1];
    const float* W_gat    = (const float*)d_in[2];
    const float* att_src  = (const float*)d_in[3];
    const float* att_dst  = (const float*)d_in[4];
    const float* b_gat    = (const float*)d_in[5];
    const float* ln1_g    = (const float*)d_in[6];
    const float* ln1_b    = (const float*)d_in[7];
    const float* ln2_g    = (const float*)d_in[8];
    const float* ln2_b    = (const float*)d_in[9];
    const float* W1       = (const float*)d_in[10];
    const float* b1       = (const float*)d_in[11];
    const float* W2       = (const float*)d_in[12];
    const float* b2       = (const float*)d_in[13];
    float* out = (float*)d_out;

    const int* edge_src = edge;
    const int* edge_dst = edge + En;

    __nv_bfloat16 *xnb, *z, *w1t, *w2t, *wgt;
    float *hmat, *asrc, *adst, *y1;
    cudaGetSymbolAddress((void**)&xnb,  g_xnb);
    cudaGetSymbolAddress((void**)&hmat, g_h);
    cudaGetSymbolAddress((void**)&asrc, g_asrc);
    cudaGetSymbolAddress((void**)&adst, g_adst);
    cudaGetSymbolAddress((void**)&y1,   g_y1);
    cudaGetSymbolAddress((void**)&z,    g_z);
    cudaGetSymbolAddress((void**)&w1t,  g_w1t);
    cudaGetSymbolAddress((void**)&w2t,  g_w2t);
    cudaGetSymbolAddress((void**)&wgt,  g_wgt);

    // CSR build (graph shared across batch)
    zero_cnt_kernel<<<(Tn + 256) / 256, 256>>>();
    hist_kernel<<<(NEDGE + 255) / 256, 256>>>(edge_dst);
    scan_kernel<<<1, 1024>>>();
    scatter_kernel<<<(NEDGE + 255) / 256, 256>>>(edge_src, edge_dst);

    // weight transpose+convert
    transpose_bf16<<<dim3(Cn / 32, Cn / 32), dim3(32, 32)>>>(W_gat, wgt, Cn, Cn);
    transpose_bf16<<<dim3(DFF / 32, Cn / 32), dim3(32, 32)>>>(W1, w1t, Cn, DFF);
    transpose_bf16<<<dim3(Cn / 32, DFF / 32), dim3(32, 32)>>>(W2, w2t, DFF, Cn);

    // LN1 -> bf16
    ln_bf16_kernel<<<BT, 128>>>(x, ln1_g, ln1_b, xnb);
    // h = xn @ W_gat (HMMA)
    gemm_mma<Cn, Cn, 0><<<dim3(Cn / 128, BT / 128), 256>>>(
        xnb, wgt, nullptr, nullptr, hmat, nullptr);
    // attention coefficients
    attn_coef_kernel<<<(BT * Hn) / 8, 256>>>(hmat, att_src, att_dst);
    // segment softmax + aggregation + residual
    gat_agg_kernel<<<(Bn * Tn * Hn) / 8, 256>>>(hmat, asrc, adst, x, b_gat, y1);
    // LN2 -> bf16
    ln_bf16_kernel<<<BT, 128>>>(y1, ln2_g, ln2_b, xnb);
    // FFN1: Z = relu(xn @ W1 + b1)  (bf16 out)
    gemm_mma<DFF, Cn, 1><<<dim3(DFF / 128, BT / 128), 256>>>(
        xnb, w1t, b1, nullptr, nullptr, z);
    // FFN2: out = Z @ W2 + b2 + y1 (fp32 out)
    gemm_mma<Cn, DFF, 2><<<dim3(Cn / 128, BT / 128), 256>>>(
        z, w2t, b2, y1, out, nullptr);
}

// round 5
// speedup vs baseline: 5.3150x; 1.1324x over previous
#include <cuda_runtime.h>
#include <cuda_bf16.h>
#include <cstdint>

#define Bn 8
#define Tn 4096
#define Cn 384
#define Hn 6
#define Fn 64
#define En 131072
#define DFF 1536
#define BT (Bn * Tn)             // 32768
#define NEDGE (En + Tn)          // 135168
#define NEG_SLOPE 0.2f
#define LN_EPS 1e-5f

// ---------------- scratch (__device__ globals; no allocation) ----------------
__device__ __nv_bfloat16 g_xnb[BT * Cn];     // LN output (bf16), reused LN1/LN2
__device__ __nv_bfloat16 g_hb[BT * Cn];      // GAT projection h (bf16)
__device__ float         g_asrc[BT * Hn];
__device__ float         g_adst[BT * Hn];
__device__ float         g_y1[BT * Cn];      // x + gat_out (residual 1, fp32)
__device__ __nv_bfloat16 g_z[BT * DFF];      // FFN hidden (bf16)
__device__ __nv_bfloat16 g_w1t[DFF * Cn];    // W1^T  [DFF][C]
__device__ __nv_bfloat16 g_w2t[Cn * DFF];    // W2^T  [C][DFF]
__device__ __nv_bfloat16 g_wgt[Cn * Cn];     // W_gat^T
__device__ int g_cnt[Tn + 1];
__device__ int g_off[Tn + 1];
__device__ int g_cur[Tn];
__device__ int g_csrc[NEDGE];

// ---------------- PTX helpers ----------------
__device__ __forceinline__ uint32_t smem_u32(const void* p) {
    uint32_t a;
    asm("{ .reg .u64 t; cvta.to.shared.u64 t, %1; cvt.u32.u64 %0, t; }" : "=r"(a) : "l"(p));
    return a;
}
__device__ __forceinline__ void cp_async16(uint32_t dst, const void* src) {
    asm volatile("cp.async.cg.shared.global [%0], [%1], 16;" :: "r"(dst), "l"(src) : "memory");
}
__device__ __forceinline__ void cp_commit() {
    asm volatile("cp.async.commit_group;" ::: "memory");
}
__device__ __forceinline__ void cp_wait1() {
    asm volatile("cp.async.wait_group 1;" ::: "memory");
}
__device__ __forceinline__ void cp_wait0() {
    asm volatile("cp.async.wait_group 0;" ::: "memory");
}
__device__ __forceinline__ void ldmat_x4(uint32_t& r0, uint32_t& r1, uint32_t& r2, uint32_t& r3,
                                         uint32_t addr) {
    asm volatile("ldmatrix.sync.aligned.m8n8.x4.shared.b16 {%0,%1,%2,%3}, [%4];"
                 : "=r"(r0), "=r"(r1), "=r"(r2), "=r"(r3) : "r"(addr));
}
__device__ __forceinline__ void mma_bf16(float* d, const uint32_t* a, const uint32_t* b) {
    asm volatile(
        "mma.sync.aligned.m16n8k16.row.col.f32.bf16.bf16.f32 "
        "{%0,%1,%2,%3}, {%4,%5,%6,%7}, {%8,%9}, {%0,%1,%2,%3};"
        : "+f"(d[0]), "+f"(d[1]), "+f"(d[2]), "+f"(d[3])
        : "r"(a[0]), "r"(a[1]), "r"(a[2]), "r"(a[3]), "r"(b[0]), "r"(b[1]));
}

// SW64 swizzle for 64-byte smem rows (conflict-free for ldmatrix + cp.async)
__device__ __forceinline__ uint32_t sw64(uint32_t off) {
    return off ^ ((off >> 3) & 0x30);
}

// ---------------- bf16 HMMA GEMM: D[M,N] = A[M,K] @ Bt[N,K]^T ----------------
// MODE 0: fp32 out plain; MODE 1: bf16 out bias+relu; MODE 2: fp32 out bias+residual
// MODE 3: bf16 out plain
// 128x128 CTA tile, BK=32, double-buffered cp.async, 8 warps (2M x 4N), warp 64x32.
template <int N, int K, int MODE>
__global__ __launch_bounds__(256, 2) void gemm_mma(
    const __nv_bfloat16* __restrict__ A,
    const __nv_bfloat16* __restrict__ Bt,
    const float* __restrict__ bias,
    const float* __restrict__ res,
    float* __restrict__ outf,
    __nv_bfloat16* __restrict__ outb)
{
    __shared__ __align__(1024) unsigned char smem[32768]; // [stage][A 8KB | B 8KB]
    const uint32_t sbase = smem_u32(smem);

    int tid = threadIdx.x;
    int wid = tid >> 5;
    int lane = tid & 31;
    int bm = blockIdx.y * 128;
    int bn = blockIdx.x * 128;
    int wm = (wid & 1) * 64;
    int wn = (wid >> 1) * 32;

    float acc[4][4][4];
#pragma unroll
    for (int i = 0; i < 4; i++)
#pragma unroll
        for (int j = 0; j < 4; j++)
#pragma unroll
            for (int d = 0; d < 4; d++) acc[i][j][d] = 0.f;

    const int KT = K / 32;

    auto load_stage = [&](int kt, int s) {
        int k0 = kt * 32;
        uint32_t sA = sbase + s * 16384;
        uint32_t sB = sA + 8192;
#pragma unroll
        for (int i = 0; i < 2; i++) {
            int idx = tid + i * 256;          // 0..511
            int r = idx >> 2, c = idx & 3;
            uint32_t sw = sw64(r * 64 + c * 16);
            cp_async16(sA + sw, A + (size_t)(bm + r) * K + k0 + c * 8);
            cp_async16(sB + sw, Bt + (size_t)(bn + r) * K + k0 + c * 8);
        }
    };

    load_stage(0, 0);
    cp_commit();

    for (int kt = 0; kt < KT; kt++) {
        if (kt + 1 < KT) {
            load_stage(kt + 1, (kt + 1) & 1);
            cp_commit();
            cp_wait1();
        } else {
            cp_wait0();
        }
        __syncthreads();

        uint32_t sA = sbase + (kt & 1) * 16384;
        uint32_t sB = sA + 8192;
#pragma unroll
        for (int ks = 0; ks < 2; ks++) {
            uint32_t af[4][4];
            uint32_t bf[4][2];
#pragma unroll
            for (int mi = 0; mi < 4; mi++) {
                int row = wm + mi * 16 + (lane & 15);
                int colb = (ks * 16 + ((lane >> 4) << 3)) * 2;
                ldmat_x4(af[mi][0], af[mi][1], af[mi][2], af[mi][3],
                         sA + sw64(row * 64 + colb));
            }
#pragma unroll
            for (int nj = 0; nj < 2; nj++) {
                int nrow = wn + nj * 16 + (lane & 7) + ((lane >> 4) << 3);
                int kcolb = (ks * 16 + (((lane >> 3) & 1) << 3)) * 2;
                uint32_t r0, r1, r2, r3;
                ldmat_x4(r0, r1, r2, r3, sB + sw64(nrow * 64 + kcolb));
                bf[nj * 2][0] = r0; bf[nj * 2][1] = r1;
                bf[nj * 2 + 1][0] = r2; bf[nj * 2 + 1][1] = r3;
            }
#pragma unroll
            for (int mi = 0; mi < 4; mi++)
#pragma unroll
                for (int ni = 0; ni < 4; ni++)
                    mma_bf16(acc[mi][ni], af[mi], bf[ni]);
        }
        __syncthreads();
    }

    int rq = lane >> 2;
    int cq = (lane & 3) * 2;
#pragma unroll
    for (int mi = 0; mi < 4; mi++) {
#pragma unroll
        for (int ni = 0; ni < 4; ni++) {
            int gm = bm + wm + mi * 16 + rq;
            int gn = bn + wn + ni * 8 + cq;
            float v0 = acc[mi][ni][0], v1 = acc[mi][ni][1];
            float v2 = acc[mi][ni][2], v3 = acc[mi][ni][3];
            if (MODE == 0) {
                *(float2*)(outf + (size_t)gm * N + gn) = make_float2(v0, v1);
                *(float2*)(outf + (size_t)(gm + 8) * N + gn) = make_float2(v2, v3);
            } else if (MODE == 1) {
                float b0 = bias[gn], b1 = bias[gn + 1];
                __nv_bfloat162 p0, p1;
                p0.x = __float2bfloat16(fmaxf(v0 + b0, 0.f));
                p0.y = __float2bfloat16(fmaxf(v1 + b1, 0.f));
                p1.x = __float2bfloat16(fmaxf(v2 + b0, 0.f));
                p1.y = __float2bfloat16(fmaxf(v3 + b1, 0.f));
                *(__nv_bfloat162*)(outb + (size_t)gm * N + gn) = p0;
                *(__nv_bfloat162*)(outb + (size_t)(gm + 8) * N + gn) = p1;
            } else if (MODE == 3) {
                __nv_bfloat162 p0, p1;
                p0.x = __float2bfloat16(v0); p0.y = __float2bfloat16(v1);
                p1.x = __float2bfloat16(v2); p1.y = __float2bfloat16(v3);
                *(__nv_bfloat162*)(outb + (size_t)gm * N + gn) = p0;
                *(__nv_bfloat162*)(outb + (size_t)(gm + 8) * N + gn) = p1;
            } else {
                float b0 = bias[gn], b1 = bias[gn + 1];
                float2 r0 = *(const float2*)(res + (size_t)gm * N + gn);
                float2 r1 = *(const float2*)(res + (size_t)(gm + 8) * N + gn);
                *(float2*)(outf + (size_t)gm * N + gn) = make_float2(v0 + b0 + r0.x, v1 + b1 + r0.y);
                *(float2*)(outf + (size_t)(gm + 8) * N + gn) = make_float2(v2 + b0 + r1.x, v3 + b1 + r1.y);
            }
        }
    }
}

// ---------------- weight transpose + fp32->bf16 ----------------
__global__ void transpose_bf16(const float* __restrict__ src, __nv_bfloat16* __restrict__ dst,
                               int Rs, int Cs) {
    __shared__ float t[32][33];
    int c = blockIdx.x * 32 + threadIdx.x;
    int r = blockIdx.y * 32 + threadIdx.y;
    t[threadIdx.y][threadIdx.x] = src[(size_t)r * Cs + c];
    __syncthreads();
    int oc = blockIdx.y * 32 + threadIdx.x;
    int orr = blockIdx.x * 32 + threadIdx.y;
    dst[(size_t)orr * Rs + oc] = __float2bfloat16(t[threadIdx.x][threadIdx.y]);
}

// ---------------- LayerNorm (fp32 in, bf16 out) ----------------
__global__ void ln_bf16_kernel(const float* __restrict__ x, const float* __restrict__ g,
                               const float* __restrict__ b, __nv_bfloat16* __restrict__ out) {
    int row = blockIdx.x;
    int tid = threadIdx.x; // 128
    const float* xr = x + (size_t)row * Cn;
    float v0 = xr[tid], v1 = xr[tid + 128], v2 = xr[tid + 256];
    float s  = v0 + v1 + v2;
    float s2 = v0 * v0 + v1 * v1 + v2 * v2;
#pragma unroll
    for (int o = 16; o; o >>= 1) {
        s  += __shfl_xor_sync(0xffffffffu, s,  o);
        s2 += __shfl_xor_sync(0xffffffffu, s2, o);
    }
    __shared__ float ps[4], ps2[4];
    if ((tid & 31) == 0) { ps[tid >> 5] = s; ps2[tid >> 5] = s2; }
    __syncthreads();
    s  = ps[0] + ps[1] + ps[2] + ps[3];
    s2 = ps2[0] + ps2[1] + ps2[2] + ps2[3];
    float mu  = s * (1.0f / Cn);
    float var = s2 * (1.0f / Cn) - mu * mu;
    float inv = rsqrtf(var + LN_EPS);
    __nv_bfloat16* orow = out + (size_t)row * Cn;
    orow[tid]       = __float2bfloat16((v0 - mu) * inv * g[tid]       + b[tid]);
    orow[tid + 128] = __float2bfloat16((v1 - mu) * inv * g[tid + 128] + b[tid + 128]);
    orow[tid + 256] = __float2bfloat16((v2 - mu) * inv * g[tid + 256] + b[tid + 256]);
}

// ---------------- attention coefficients: warp per (node, head), bf16 h ----------------
__global__ void attn_coef_kernel(const __nv_bfloat16* __restrict__ Hm,
                                 const float* __restrict__ att_src,
                                 const float* __restrict__ att_dst) {
    int w = blockIdx.x * 8 + (threadIdx.x >> 5);
    int lane = threadIdx.x & 31;
    if (w >= BT * Hn) return;
    int h = w % Hn;
    int n = w / Hn;
    const __nv_bfloat16* hr = Hm + (size_t)n * Cn + h * Fn;
    __nv_bfloat162 hv = ((const __nv_bfloat162*)hr)[lane];
    float hx = __bfloat162float(hv.x), hy = __bfloat162float(hv.y);
    float2 a1 = ((const float2*)(att_src + h * Fn))[lane];
    float2 a2 = ((const float2*)(att_dst + h * Fn))[lane];
    float s1 = hx * a1.x + hy * a1.y;
    float s2 = hx * a2.x + hy * a2.y;
#pragma unroll
    for (int o = 16; o; o >>= 1) {
        s1 += __shfl_xor_sync(0xffffffffu, s1, o);
        s2 += __shfl_xor_sync(0xffffffffu, s2, o);
    }
    if (lane == 0) { g_asrc[w] = s1; g_adst[w] = s2; }
}

// ---------------- CSR build ----------------
__global__ void zero_cnt_kernel() {
    int i = blockIdx.x * blockDim.x + threadIdx.x;
    if (i <= Tn) g_cnt[i] = 0;
}
__global__ void hist_kernel(const int* __restrict__ edge_dst) {
    int e = blockIdx.x * blockDim.x + threadIdx.x;
    if (e >= NEDGE) return;
    int d = (e < En) ? edge_dst[e] : (e - En);
    atomicAdd(&g_cnt[d], 1);
}
__global__ void scan_kernel() {
    __shared__ int sm[1024];
    int t = threadIdx.x;
    int c0 = g_cnt[4 * t + 0], c1 = g_cnt[4 * t + 1];
    int c2 = g_cnt[4 * t + 2], c3 = g_cnt[4 * t + 3];
    int val = c0 + c1 + c2 + c3;
    sm[t] = val;
    __syncthreads();
    for (int d = 1; d < 1024; d <<= 1) {
        int v = (t >= d) ? sm[t - d] : 0;
        __syncthreads();
        if (t >= d) sm[t] += v;
        __syncthreads();
    }
    int base = sm[t] - val;
    g_off[4 * t + 0] = base;                g_cur[4 * t + 0] = base;
    g_off[4 * t + 1] = base + c0;           g_cur[4 * t + 1] = base + c0;
    g_off[4 * t + 2] = base + c0 + c1;      g_cur[4 * t + 2] = base + c0 + c1;
    g_off[4 * t + 3] = base + c0 + c1 + c2; g_cur[4 * t + 3] = base + c0 + c1 + c2;
    if (t == 1023) g_off[Tn] = sm[1023];
}
__global__ void scatter_kernel(const int* __restrict__ edge_src,
                               const int* __restrict__ edge_dst) {
    int e = blockIdx.x * blockDim.x + threadIdx.x;
    if (e >= NEDGE) return;
    int s, d;
    if (e < En) { s = edge_src[e]; d = edge_dst[e]; }
    else        { s = e - En;      d = e - En; }
    int p = atomicAdd(&g_cur[d], 1);
    g_csrc[p] = s;
}

// ---------------- GAT aggregation v2: warp per (b,t,h), 2 edges/iter ----------------
// No max-subtraction (|alpha| << 80, exp safe). Half-warps own alternating edges;
// each lane loads 4 bf16 features (8B). Final shfl-xor(16) merge.
__global__ void gat_agg_kernel(const __nv_bfloat16* __restrict__ Hb,
                               const float* __restrict__ asrc,
                               const float* __restrict__ adst,
                               const float* __restrict__ x,
                               const float* __restrict__ bgat,
                               float* __restrict__ y1) {
    int w = blockIdx.x * 8 + (threadIdx.x >> 5);
    int lane = threadIdx.x & 31;
    if (w >= Bn * Tn * Hn) return;
    int h = w % Hn;
    int n = w / Hn;      // b*T + t
    int t = n % Tn;
    int b = n / Tn;
    int half = lane >> 4;     // 0/1
    int sub = lane & 15;      // feature group: 4 bf16 each
    int beg = g_off[t], end = g_off[t + 1];
    int nb = b * Tn;          // base row for this batch
    float a_d = adst[(size_t)n * Hn + h];

    float den = 0.f;
    float acc0 = 0.f, acc1 = 0.f, acc2 = 0.f, acc3 = 0.f;

    for (int e = beg + half; e < end; e += 2) {
        int s = g_csrc[e];
        int row = nb + s;
        float al = asrc[(size_t)row * Hn + h] + a_d;
        al = (al >= 0.f) ? al : NEG_SLOPE * al;
        float wgt = __expf(al);
        den += wgt;
        uint2 raw = *(const uint2*)(Hb + (size_t)row * Cn + h * Fn + sub * 4);
        __nv_bfloat162 p0 = *(__nv_bfloat162*)&raw.x;
        __nv_bfloat162 p1 = *(__nv_bfloat162*)&raw.y;
        acc0 += wgt * __bfloat162float(p0.x);
        acc1 += wgt * __bfloat162float(p0.y);
        acc2 += wgt * __bfloat162float(p1.x);
        acc3 += wgt * __bfloat162float(p1.y);
    }
    // merge halves
    den  += __shfl_xor_sync(0xffffffffu, den,  16);
    acc0 += __shfl_xor_sync(0xffffffffu, acc0, 16);
    acc1 += __shfl_xor_sync(0xffffffffu, acc1, 16);
    acc2 += __shfl_xor_sync(0xffffffffu, acc2, 16);
    acc3 += __shfl_xor_sync(0xffffffffu, acc3, 16);

    if (half == 0) {
        float inv = 1.f / den;
        int c = h * Fn + sub * 4;
        size_t o = (size_t)n * Cn + c;
        float4 xo = *(const float4*)(x + o);
        float4 bg = *(const float4*)(bgat + c);
        float4 r;
        r.x = xo.x + acc0 * inv + bg.x;
        r.y = xo.y + acc1 * inv + bg.y;
        r.z = xo.z + acc2 * inv + bg.z;
        r.w = xo.w + acc3 * inv + bg.w;
        *(float4*)(y1 + o) = r;
    }
}

// ---------------- launch ----------------
extern "C" void kernel_launch(void* const* d_in, const int* in_sizes, int n_in,
                              void* d_out, int out_size) {
    const float* x        = (const float*)d_in[0];
    const int*   edge     = (const int*)d_in[1];
    const float* W_gat    = (const float*)d_in[2];
    const float* att_src  = (const float*)d_in[3];
    const float* att_dst  = (const float*)d_in[4];
    const float* b_gat    = (const float*)d_in[5];
    const float* ln1_g    = (const float*)d_in[6];
    const float* ln1_b    = (const float*)d_in[7];
    const float* ln2_g    = (const float*)d_in[8];
    const float* ln2_b    = (const float*)d_in[9];
    const float* W1       = (const float*)d_in[10];
    const float* b1       = (const float*)d_in[11];
    const float* W2       = (const float*)d_in[12];
    const float* b2       = (const float*)d_in[13];
    float* out = (float*)d_out;

    const int* edge_src = edge;
    const int* edge_dst = edge + En;

    __nv_bfloat16 *xnb, *hb, *z, *w1t, *w2t, *wgt;
    float *asrc, *adst, *y1;
    cudaGetSymbolAddress((void**)&xnb,  g_xnb);
    cudaGetSymbolAddress((void**)&hb,   g_hb);
    cudaGetSymbolAddress((void**)&asrc, g_asrc);
    cudaGetSymbolAddress((void**)&adst, g_adst);
    cudaGetSymbolAddress((void**)&y1,   g_y1);
    cudaGetSymbolAddress((void**)&z,    g_z);
    cudaGetSymbolAddress((void**)&w1t,  g_w1t);
    cudaGetSymbolAddress((void**)&w2t,  g_w2t);
    cudaGetSymbolAddress((void**)&wgt,  g_wgt);

    // CSR build (graph shared across batch)
    zero_cnt_kernel<<<(Tn + 256) / 256, 256>>>();
    hist_kernel<<<(NEDGE + 255) / 256, 256>>>(edge_dst);
    scan_kernel<<<1, 1024>>>();
    scatter_kernel<<<(NEDGE + 255) / 256, 256>>>(edge_src, edge_dst);

    // weight transpose+convert
    transpose_bf16<<<dim3(Cn / 32, Cn / 32), dim3(32, 32)>>>(W_gat, wgt, Cn, Cn);
    transpose_bf16<<<dim3(DFF / 32, Cn / 32), dim3(32, 32)>>>(W1, w1t, Cn, DFF);
    transpose_bf16<<<dim3(Cn / 32, DFF / 32), dim3(32, 32)>>>(W2, w2t, DFF, Cn);

    // LN1 -> bf16
    ln_bf16_kernel<<<BT, 128>>>(x, ln1_g, ln1_b, xnb);
    // h = xn @ W_gat (HMMA, bf16 out)
    gemm_mma<Cn, Cn, 3><<<dim3(Cn / 128, BT / 128), 256>>>(
        xnb, wgt, nullptr, nullptr, nullptr, hb);
    // attention coefficients
    attn_coef_kernel<<<(BT * Hn) / 8, 256>>>(hb, att_src, att_dst);
    // segment softmax + aggregation + residual
    gat_agg_kernel<<<(Bn * Tn * Hn) / 8, 256>>>(hb, asrc, adst, x, b_gat, y1);
    // LN2 -> bf16
    ln_bf16_kernel<<<BT, 128>>>(y1, ln2_g, ln2_b, xnb);
    // FFN1: Z = relu(xn @ W1 + b1)  (bf16 out)
    gemm_mma<DFF, Cn, 1><<<dim3(DFF / 128, BT / 128), 256>>>(
        xnb, w1t, b1, nullptr, nullptr, z);
    // FFN2: out = Z @ W2 + b2 + y1 (fp32 out)
    gemm_mma<Cn, DFF, 2><<<dim3(Cn / 128, BT / 128), 256>>>(
        z, w2t, b2, y1, out, nullptr);
}